// round 5
// baseline (speedup 1.0000x reference)
#include <cuda_runtime.h>

// COO SpMM with sorted rows -> CSR two-phase, no atomics / no smem / no memset.
//   Phase A: row_ptr[r] = lower_bound(rows, r)
//   Phase B: HALF-warp per row (warp = pair of rows), lane owns 4 features
//            (float4): one LDG.128 gathers 2 edges per warp-instruction.
// Inputs: seq [50000*64 f32], vals [E f32], rows [E i32], cols [E i32]
// Output: [1, 50000, 64] f32

#define D_FEAT 64
#define MAX_NODES 50001

__device__ int g_row_ptr[MAX_NODES + 1];

__global__ void build_row_ptr_kernel(const int* __restrict__ rows,
                                     int n_edges, int n_nodes) {
    int r = blockIdx.x * blockDim.x + threadIdx.x;
    if (r > n_nodes) return;
    int lo = 0, hi = n_edges;
    while (lo < hi) {
        int mid = (lo + hi) >> 1;
        if (rows[mid] < r) lo = mid + 1; else hi = mid;
    }
    g_row_ptr[r] = lo;
}

#define FULL 0xffffffffu

__global__ __launch_bounds__(256)
void spmm_csr_pair_kernel(const float* __restrict__ seq,
                          const float* __restrict__ vals,
                          const int* __restrict__ cols,
                          float* __restrict__ out,
                          int n_nodes) {
    const int warpId = (blockIdx.x * blockDim.x + threadIdx.x) >> 5;
    const int lane   = threadIdx.x & 31;
    const int half   = lane >> 4;        // which row of the pair
    const int fl     = lane & 15;        // feature lane: 4 floats
    const int src0   = half << 4;        // shfl source base for my half

    const int row = 2 * warpId + half;
    int beg = 0, end = 0;
    if (row < n_nodes) { beg = g_row_ptr[row]; end = g_row_ptr[row + 1]; }
    const int len = end - beg;

    // Warp-uniform tile count = max over the two halves.
    int T = (len + 15) >> 4;
    T = max(T, __shfl_xor_sync(FULL, T, 16));

    const float4* __restrict__ seq4 = reinterpret_cast<const float4*>(seq);
    float4 acc = make_float4(0.f, 0.f, 0.f, 0.f);

    for (int t = 0; t < T; ++t) {
        const int base = beg + (t << 4);
        const int idx  = base + fl;
        int   c = 0;
        float v = 0.f;
        if (idx < end) { c = cols[idx]; v = vals[idx]; }   // coalesced 64B/half

        int cnt = min(16, end - base);
        cnt = max(cnt, 0);
        // warp-uniform inner bound, rounded up to 4 (inactive lanes: c=0,v=0
        // -> gathers hit seq[0] in L1, FMAs add 0; no divergence, no L2 waste)
        int cmax = max(cnt, __shfl_xor_sync(FULL, cnt, 16));
        cmax = (cmax + 3) & ~3;

        for (int jj = 0; jj < cmax; jj += 4) {
            const int   c0 = __shfl_sync(FULL, c, src0 + jj);
            const int   c1 = __shfl_sync(FULL, c, src0 + jj + 1);
            const int   c2 = __shfl_sync(FULL, c, src0 + jj + 2);
            const int   c3 = __shfl_sync(FULL, c, src0 + jj + 3);
            const float v0 = __shfl_sync(FULL, v, src0 + jj);
            const float v1 = __shfl_sync(FULL, v, src0 + jj + 1);
            const float v2 = __shfl_sync(FULL, v, src0 + jj + 2);
            const float v3 = __shfl_sync(FULL, v, src0 + jj + 3);

            // 4 back-to-back LDG.128, each covering both halves (2 edges).
            const float4 x0 = seq4[c0 * (D_FEAT / 4) + fl];
            const float4 x1 = seq4[c1 * (D_FEAT / 4) + fl];
            const float4 x2 = seq4[c2 * (D_FEAT / 4) + fl];
            const float4 x3 = seq4[c3 * (D_FEAT / 4) + fl];

            acc.x = fmaf(v0, x0.x, acc.x); acc.y = fmaf(v0, x0.y, acc.y);
            acc.z = fmaf(v0, x0.z, acc.z); acc.w = fmaf(v0, x0.w, acc.w);
            acc.x = fmaf(v1, x1.x, acc.x); acc.y = fmaf(v1, x1.y, acc.y);
            acc.z = fmaf(v1, x1.z, acc.z); acc.w = fmaf(v1, x1.w, acc.w);
            acc.x = fmaf(v2, x2.x, acc.x); acc.y = fmaf(v2, x2.y, acc.y);
            acc.z = fmaf(v2, x2.z, acc.z); acc.w = fmaf(v2, x2.w, acc.w);
            acc.x = fmaf(v3, x3.x, acc.x); acc.y = fmaf(v3, x3.y, acc.y);
            acc.z = fmaf(v3, x3.z, acc.z); acc.w = fmaf(v3, x3.w, acc.w);
        }
    }

    // One coalesced non-atomic float4 store per row (empty rows write zeros).
    if (row < n_nodes)
        reinterpret_cast<float4*>(out)[row * (D_FEAT / 4) + fl] = acc;
}

extern "C" void kernel_launch(void* const* d_in, const int* in_sizes, int n_in,
                              void* d_out, int out_size) {
    const float* seq  = (const float*)d_in[0];
    const float* vals = (const float*)d_in[1];
    const int*   rows = (const int*)d_in[2];
    const int*   cols = (const int*)d_in[3];
    float*       out  = (float*)d_out;
    const int n_edges = in_sizes[1];
    const int n_nodes = out_size / D_FEAT;   // 50000

    const int tA = 256;
    build_row_ptr_kernel<<<(n_nodes + 1 + tA) / tA, tA>>>(rows, n_edges, n_nodes);

    // Phase B: warp per row-PAIR, 8 warps per block.
    const int n_warps  = (n_nodes + 1) / 2;              // 25000
    const int n_blocks = (n_warps + 7) / 8;              // 3125
    spmm_csr_pair_kernel<<<n_blocks, 256>>>(seq, vals, cols, out, n_nodes);
}

// round 6
// speedup vs baseline: 1.1257x; 1.1257x over previous
#include <cuda_runtime.h>

// COO SpMM with sorted rows -> CSR two-phase, no atomics / no smem / no memset.
//   Phase A: row_ptr[r] = lower_bound(rows, r)
//   Phase B: warp per row; the two half-warps split the row's EDGES
//            (even/odd positions) so one LDG.128 gathers 2 edges; lane owns
//            4 features. Cross-half shfl reduction, single store per row.
// Inputs: seq [50000*64 f32], vals [E f32], rows [E i32], cols [E i32]
// Output: [1, 50000, 64] f32

#define D_FEAT 64
#define MAX_NODES 50001
#define FULL 0xffffffffu

__device__ int g_row_ptr[MAX_NODES + 1];

__global__ void build_row_ptr_kernel(const int* __restrict__ rows,
                                     int n_edges, int n_nodes) {
    int r = blockIdx.x * blockDim.x + threadIdx.x;
    if (r > n_nodes) return;
    int lo = 0, hi = n_edges;
    while (lo < hi) {
        int mid = (lo + hi) >> 1;
        if (rows[mid] < r) lo = mid + 1; else hi = mid;
    }
    g_row_ptr[r] = lo;
}

__global__ __launch_bounds__(256, 6)
void spmm_csr_split_kernel(const float* __restrict__ seq,
                           const float* __restrict__ vals,
                           const int* __restrict__ cols,
                           float* __restrict__ out,
                           int n_nodes) {
    const int row  = (blockIdx.x * blockDim.x + threadIdx.x) >> 5;
    const int lane = threadIdx.x & 31;
    const int half = lane >> 4;       // 0: even-position edges, 1: odd
    const int fl   = lane & 15;       // feature lane: 4 floats
    if (row >= n_nodes) return;

    const int beg = g_row_ptr[row];
    const int end = g_row_ptr[row + 1];
    const int len = end - beg;

    const float4* __restrict__ seq4 = reinterpret_cast<const float4*>(seq);
    float4 acc = make_float4(0.f, 0.f, 0.f, 0.f);

    const int tiles = (len + 31) >> 5;
    for (int t = 0; t < tiles; ++t) {
        const int base = beg + (t << 5);
        const int idx  = base + lane;
        int   c = 0;
        float v = 0.f;
        if (idx < end) { c = cols[idx]; v = vals[idx]; }  // coalesced 32 edges

        const int cnt = min(32, end - base);
        // Half h consumes tile positions 2k+h. Warp-uniform bound rounded to
        // unroll-4; overshoot slots have c=0,v=0 -> L1-hit dummy gathers.
        const int kU = ((cnt + 1) >> 1 + 0);
        const int kU4 = (kU + 3) & ~3;                    // <= 16

        for (int k = 0; k < kU4; k += 4) {
            const int s = 2 * k + half;
            const int   c0 = __shfl_sync(FULL, c, s);
            const int   c1 = __shfl_sync(FULL, c, s + 2);
            const int   c2 = __shfl_sync(FULL, c, s + 4);
            const int   c3 = __shfl_sync(FULL, c, s + 6);
            const float v0 = __shfl_sync(FULL, v, s);
            const float v1 = __shfl_sync(FULL, v, s + 2);
            const float v2 = __shfl_sync(FULL, v, s + 4);
            const float v3 = __shfl_sync(FULL, v, s + 6);

            // 4 back-to-back LDG.128; each warp-instruction covers 2 edges.
            const float4 x0 = seq4[c0 * (D_FEAT / 4) + fl];
            const float4 x1 = seq4[c1 * (D_FEAT / 4) + fl];
            const float4 x2 = seq4[c2 * (D_FEAT / 4) + fl];
            const float4 x3 = seq4[c3 * (D_FEAT / 4) + fl];

            acc.x = fmaf(v0, x0.x, acc.x); acc.y = fmaf(v0, x0.y, acc.y);
            acc.z = fmaf(v0, x0.z, acc.z); acc.w = fmaf(v0, x0.w, acc.w);
            acc.x = fmaf(v1, x1.x, acc.x); acc.y = fmaf(v1, x1.y, acc.y);
            acc.z = fmaf(v1, x1.z, acc.z); acc.w = fmaf(v1, x1.w, acc.w);
            acc.x = fmaf(v2, x2.x, acc.x); acc.y = fmaf(v2, x2.y, acc.y);
            acc.z = fmaf(v2, x2.z, acc.z); acc.w = fmaf(v2, x2.w, acc.w);
            acc.x = fmaf(v3, x3.x, acc.x); acc.y = fmaf(v3, x3.y, acc.y);
            acc.z = fmaf(v3, x3.z, acc.z); acc.w = fmaf(v3, x3.w, acc.w);
        }
    }

    // Combine the two halves (they hold the same 4 features for this row).
    acc.x += __shfl_xor_sync(FULL, acc.x, 16);
    acc.y += __shfl_xor_sync(FULL, acc.y, 16);
    acc.z += __shfl_xor_sync(FULL, acc.z, 16);
    acc.w += __shfl_xor_sync(FULL, acc.w, 16);

    if (half == 0)   // 16 lanes x float4 = 256B coalesced; zeros for empty rows
        reinterpret_cast<float4*>(out)[row * (D_FEAT / 4) + fl] = acc;
}

extern "C" void kernel_launch(void* const* d_in, const int* in_sizes, int n_in,
                              void* d_out, int out_size) {
    const float* seq  = (const float*)d_in[0];
    const float* vals = (const float*)d_in[1];
    const int*   rows = (const int*)d_in[2];
    const int*   cols = (const int*)d_in[3];
    float*       out  = (float*)d_out;
    const int n_edges = in_sizes[1];
    const int n_nodes = out_size / D_FEAT;   // 50000

    const int tA = 256;
    build_row_ptr_kernel<<<(n_nodes + 1 + tA) / tA, tA>>>(rows, n_edges, n_nodes);

    // Phase B: one warp per row, 8 warps per block.
    spmm_csr_split_kernel<<<(n_nodes + 7) / 8, 256>>>(seq, vals, cols, out, n_nodes);
}

// round 7
// speedup vs baseline: 1.2664x; 1.1250x over previous
#include <cuda_runtime.h>

// COO SpMM with sorted rows -> CSR two-phase, no atomics / no smem / no memset.
//   Phase A: row_ptr[r] = lower_bound(rows, r)
//   Phase B: warp per row; half-warps take even/odd edge positions so one
//            LDG.128 gathers 2 edges. Edge meta fetched via uniform-address
//            LDG (L1 broadcast, ~16 reuses per 128B line) -- NO shuffles.
// Inputs: seq [50000*64 f32], vals [E f32], rows [E i32], cols [E i32]
// Output: [1, 50000, 64] f32

#define D_FEAT 64
#define MAX_NODES 50001
#define FULL 0xffffffffu

__device__ int g_row_ptr[MAX_NODES + 1];

__global__ void build_row_ptr_kernel(const int* __restrict__ rows,
                                     int n_edges, int n_nodes) {
    int r = blockIdx.x * blockDim.x + threadIdx.x;
    if (r > n_nodes) return;
    int lo = 0, hi = n_edges;
    while (lo < hi) {
        int mid = (lo + hi) >> 1;
        if (rows[mid] < r) lo = mid + 1; else hi = mid;
    }
    g_row_ptr[r] = lo;
}

__global__ __launch_bounds__(128, 12)
void spmm_csr_uload_kernel(const float* __restrict__ seq,
                           const float* __restrict__ vals,
                           const int* __restrict__ cols,
                           float* __restrict__ out,
                           int n_nodes) {
    const int row  = (blockIdx.x * blockDim.x + threadIdx.x) >> 5;
    const int lane = threadIdx.x & 31;
    const int half = lane >> 4;       // 0: even-position edges, 1: odd
    const int fl   = lane & 15;       // feature lane: 4 floats
    if (row >= n_nodes) return;

    const int beg = g_row_ptr[row];
    const int end = g_row_ptr[row + 1];

    const float4* __restrict__ seq4 = reinterpret_cast<const float4*>(seq);
    float4 acc = make_float4(0.f, 0.f, 0.f, 0.f);

    int i = beg + half;

    // Main loop: 4 edges per half per iteration. Meta loads are uniform
    // within a half (L1 broadcast); the 4 gathers issue back-to-back with
    // addresses ready early (no shfl chain). One LDG.128 covers 2 edges
    // (the two halves gather different rows in the same instruction).
    for (; i + 6 < end; i += 8) {
        const int c0 = cols[i]     * (D_FEAT / 4);
        const int c1 = cols[i + 2] * (D_FEAT / 4);
        const int c2 = cols[i + 4] * (D_FEAT / 4);
        const int c3 = cols[i + 6] * (D_FEAT / 4);
        const float v0 = vals[i];
        const float v1 = vals[i + 2];
        const float v2 = vals[i + 4];
        const float v3 = vals[i + 6];

        const float4 x0 = seq4[c0 + fl];
        const float4 x1 = seq4[c1 + fl];
        const float4 x2 = seq4[c2 + fl];
        const float4 x3 = seq4[c3 + fl];

        acc.x = fmaf(v0, x0.x, acc.x); acc.y = fmaf(v0, x0.y, acc.y);
        acc.z = fmaf(v0, x0.z, acc.z); acc.w = fmaf(v0, x0.w, acc.w);
        acc.x = fmaf(v1, x1.x, acc.x); acc.y = fmaf(v1, x1.y, acc.y);
        acc.z = fmaf(v1, x1.z, acc.z); acc.w = fmaf(v1, x1.w, acc.w);
        acc.x = fmaf(v2, x2.x, acc.x); acc.y = fmaf(v2, x2.y, acc.y);
        acc.z = fmaf(v2, x2.z, acc.z); acc.w = fmaf(v2, x2.w, acc.w);
        acc.x = fmaf(v3, x3.x, acc.x); acc.y = fmaf(v3, x3.y, acc.y);
        acc.z = fmaf(v3, x3.z, acc.z); acc.w = fmaf(v3, x3.w, acc.w);
    }

    // Remainder (<= 3 edges per half; halves differ by <= 1 edge).
    for (; i < end; i += 2) {
        const int   c = cols[i] * (D_FEAT / 4);
        const float v = vals[i];
        const float4 x = seq4[c + fl];
        acc.x = fmaf(v, x.x, acc.x); acc.y = fmaf(v, x.y, acc.y);
        acc.z = fmaf(v, x.z, acc.z); acc.w = fmaf(v, x.w, acc.w);
    }

    // Combine the two halves (same 4 features, even+odd partial sums).
    acc.x += __shfl_xor_sync(FULL, acc.x, 16);
    acc.y += __shfl_xor_sync(FULL, acc.y, 16);
    acc.z += __shfl_xor_sync(FULL, acc.z, 16);
    acc.w += __shfl_xor_sync(FULL, acc.w, 16);

    if (half == 0)   // 16 lanes x float4 = 256B coalesced; zeros if empty row
        reinterpret_cast<float4*>(out)[row * (D_FEAT / 4) + fl] = acc;
}

extern "C" void kernel_launch(void* const* d_in, const int* in_sizes, int n_in,
                              void* d_out, int out_size) {
    const float* seq  = (const float*)d_in[0];
    const float* vals = (const float*)d_in[1];
    const int*   rows = (const int*)d_in[2];
    const int*   cols = (const int*)d_in[3];
    float*       out  = (float*)d_out;
    const int n_edges = in_sizes[1];
    const int n_nodes = out_size / D_FEAT;   // 50000

    const int tA = 256;
    build_row_ptr_kernel<<<(n_nodes + 1 + tA) / tA, tA>>>(rows, n_edges, n_nodes);

    // Phase B: one warp per row, 4 warps per 128-thread block.
    spmm_csr_uload_kernel<<<(n_nodes + 3) / 4, 128>>>(seq, vals, cols, out, n_nodes);
}